// round 1
// baseline (speedup 1.0000x reference)
#include <cuda_runtime.h>
#include <cstdint>

// Problem constants
#define DIMM   1024
#define HEADS  16
#define DHEAD  64
#define SEQ    2048
#define BATCH  4
#define ROWS   (BATCH*SEQ)      // 8192
#define BH     (BATCH*HEADS)    // 64
#define NQKV   (3*DIMM)         // 3072
#define ATTN_SCALE 0.125f       // 64^-0.5

// ---------------------------------------------------------------------------
// Scratch (static device allocations; no cudaMalloc allowed)
// ---------------------------------------------------------------------------
__device__ float g_xn[(size_t)ROWS * DIMM];            // 32 MB  layernormed x
__device__ float g_q [(size_t)BH * SEQ * DHEAD];       // 32 MB  [b*h][n][d] (pre-scaled)
__device__ float g_k [(size_t)BH * SEQ * DHEAD];       // 32 MB
__device__ float g_v [(size_t)BH * SEQ * DHEAD];       // 32 MB
__device__ float g_s [(size_t)BH * SEQ * SEQ];         // 1 GB   attention scores / probs
__device__ float g_oc[(size_t)ROWS * DIMM];            // 32 MB  attn out in [b,n,(h d)] layout

// ---------------------------------------------------------------------------
// Kernel 1: LayerNorm  (one block per row, 256 threads, 4 floats/thread)
// ---------------------------------------------------------------------------
__global__ __launch_bounds__(256) void ln_kernel(const float* __restrict__ x,
                                                 const float* __restrict__ gamma,
                                                 const float* __restrict__ beta)
{
    __shared__ float sred[8];
    __shared__ float sred2[8];
    const int row = blockIdx.x;
    const int t   = threadIdx.x;

    const float4* px = (const float4*)(x + (size_t)row * DIMM);
    float4 v = px[t];

    float s = v.x + v.y + v.z + v.w;
    #pragma unroll
    for (int o = 16; o > 0; o >>= 1) s += __shfl_xor_sync(0xffffffffu, s, o);
    if ((t & 31) == 0) sred[t >> 5] = s;
    __syncthreads();
    float tot = sred[0];
    #pragma unroll
    for (int i = 1; i < 8; i++) tot += sred[i];
    const float mu = tot * (1.0f / DIMM);

    const float dx = v.x - mu, dy = v.y - mu, dz = v.z - mu, dw = v.w - mu;
    float ss = dx*dx + dy*dy + dz*dz + dw*dw;
    #pragma unroll
    for (int o = 16; o > 0; o >>= 1) ss += __shfl_xor_sync(0xffffffffu, ss, o);
    if ((t & 31) == 0) sred2[t >> 5] = ss;
    __syncthreads();
    float tv = sred2[0];
    #pragma unroll
    for (int i = 1; i < 8; i++) tv += sred2[i];
    const float rstd = rsqrtf(tv * (1.0f / DIMM) + 1e-5f);

    const float4 gg = ((const float4*)gamma)[t];
    const float4 bb = ((const float4*)beta)[t];
    float4 o;
    o.x = dx * rstd * gg.x + bb.x;
    o.y = dy * rstd * gg.y + bb.y;
    o.z = dz * rstd * gg.z + bb.z;
    o.w = dw * rstd * gg.w + bb.w;
    ((float4*)(g_xn + (size_t)row * DIMM))[t] = o;
}

// ---------------------------------------------------------------------------
// Kernel 2: QKV GEMM  C[8192,3072] = g_xn[8192,1024] @ w_qkv[1024,3072]
// 128x128 tile, BK=8, 256 threads, 8x8 per thread.
// Epilogue scatters into head-major g_q/g_k/g_v; Q is pre-scaled by 1/8.
// ---------------------------------------------------------------------------
__global__ __launch_bounds__(256, 2) void gemm_qkv(const float* __restrict__ B)
{
    __shared__ float As[8][128];
    __shared__ float Bs[8][128];
    const int tid = threadIdx.x;
    const int tx = tid & 15, ty = tid >> 4;
    const int bm = blockIdx.y * 128, bn = blockIdx.x * 128;
    const int K = DIMM, N = NQKV;

    float acc[8][8] = {};

    const int a_row = tid >> 1, a_k = (tid & 1) * 4;
    const int b_k = tid >> 5, b_n = (tid & 31) * 4;
    const float* Aptr = g_xn + (size_t)(bm + a_row) * K + a_k;
    const float* Bptr = B + (size_t)b_k * N + bn + b_n;

    float4 av = *(const float4*)(Aptr);
    float4 bv = *(const float4*)(Bptr);

    for (int k0 = 0; k0 < K; k0 += 8) {
        As[a_k + 0][a_row] = av.x;
        As[a_k + 1][a_row] = av.y;
        As[a_k + 2][a_row] = av.z;
        As[a_k + 3][a_row] = av.w;
        *(float4*)&Bs[b_k][b_n] = bv;
        __syncthreads();

        float4 av_n, bv_n;
        if (k0 + 8 < K) {
            av_n = *(const float4*)(Aptr + k0 + 8);
            bv_n = *(const float4*)(Bptr + (size_t)(k0 + 8) * N);
        }

        #pragma unroll
        for (int kk = 0; kk < 8; kk++) {
            float a[8], b[8];
            *(float4*)&a[0] = *(const float4*)&As[kk][ty * 8];
            *(float4*)&a[4] = *(const float4*)&As[kk][ty * 8 + 4];
            *(float4*)&b[0] = *(const float4*)&Bs[kk][tx * 8];
            *(float4*)&b[4] = *(const float4*)&Bs[kk][tx * 8 + 4];
            #pragma unroll
            for (int i = 0; i < 8; i++)
                #pragma unroll
                for (int j = 0; j < 8; j++)
                    acc[i][j] = fmaf(a[i], b[j], acc[i][j]);
        }
        __syncthreads();
        av = av_n; bv = bv_n;
    }

    // scatter epilogue: which 1024-block -> q/k/v, head-major layout
    const int which = bn >> 10;                  // 0,1,2
    const int cc = (bn & 1023) + tx * 8;         // col within q/k/v block
    const int h = cc >> 6, d0 = cc & 63;         // tile col span stays in one head
    float* dst = (which == 0) ? g_q : ((which == 1) ? g_k : g_v);
    const float scl = (which == 0) ? ATTN_SCALE : 1.0f;

    #pragma unroll
    for (int i = 0; i < 8; i++) {
        const int r = bm + ty * 8 + i;
        const int b = r >> 11;         // /2048
        const int n = r & 2047;
        float* pd = dst + ((size_t)((b * HEADS + h) * SEQ + n) * DHEAD + d0);
        float4 v0 = make_float4(acc[i][0]*scl, acc[i][1]*scl, acc[i][2]*scl, acc[i][3]*scl);
        float4 v1 = make_float4(acc[i][4]*scl, acc[i][5]*scl, acc[i][6]*scl, acc[i][7]*scl);
        *(float4*)pd = v0;
        *(float4*)(pd + 4) = v1;
    }
}

// ---------------------------------------------------------------------------
// Kernel 3: batched QK^T   S[bh][2048,2048] = Q[bh][2048,64] @ K[bh][2048,64]^T
// 128x128 tile, inner K = 64 (8 steps). Q already carries the 1/8 scale.
// ---------------------------------------------------------------------------
__global__ __launch_bounds__(256, 2) void gemm_qk()
{
    __shared__ float As[8][128];
    __shared__ float Bs[8][128];
    const int tid = threadIdx.x;
    const int tx = tid & 15, ty = tid >> 4;
    const int bm = blockIdx.y * 128, bn = blockIdx.x * 128;
    const int bh = blockIdx.z;

    const float* A  = g_q + (size_t)bh * SEQ * DHEAD;
    const float* Bm = g_k + (size_t)bh * SEQ * DHEAD;

    float acc[8][8] = {};
    const int lr = tid >> 1, lk = (tid & 1) * 4;
    const float* Ap = A  + (size_t)(bm + lr) * DHEAD + lk;
    const float* Bp = Bm + (size_t)(bn + lr) * DHEAD + lk;

    #pragma unroll
    for (int k0 = 0; k0 < DHEAD; k0 += 8) {
        float4 av = *(const float4*)(Ap + k0);
        float4 bv = *(const float4*)(Bp + k0);
        As[lk + 0][lr] = av.x; As[lk + 1][lr] = av.y;
        As[lk + 2][lr] = av.z; As[lk + 3][lr] = av.w;
        Bs[lk + 0][lr] = bv.x; Bs[lk + 1][lr] = bv.y;
        Bs[lk + 2][lr] = bv.z; Bs[lk + 3][lr] = bv.w;
        __syncthreads();
        #pragma unroll
        for (int kk = 0; kk < 8; kk++) {
            float a[8], b[8];
            *(float4*)&a[0] = *(const float4*)&As[kk][ty * 8];
            *(float4*)&a[4] = *(const float4*)&As[kk][ty * 8 + 4];
            *(float4*)&b[0] = *(const float4*)&Bs[kk][tx * 8];
            *(float4*)&b[4] = *(const float4*)&Bs[kk][tx * 8 + 4];
            #pragma unroll
            for (int i = 0; i < 8; i++)
                #pragma unroll
                for (int j = 0; j < 8; j++)
                    acc[i][j] = fmaf(a[i], b[j], acc[i][j]);
        }
        __syncthreads();
    }

    float* Sp = g_s + (size_t)bh * SEQ * SEQ;
    #pragma unroll
    for (int i = 0; i < 8; i++) {
        const int r = bm + ty * 8 + i;
        float* pd = Sp + (size_t)r * SEQ + bn + tx * 8;
        *(float4*)pd       = make_float4(acc[i][0], acc[i][1], acc[i][2], acc[i][3]);
        *(float4*)(pd + 4) = make_float4(acc[i][4], acc[i][5], acc[i][6], acc[i][7]);
    }
}

// ---------------------------------------------------------------------------
// Kernel 4: row softmax over g_s (131072 rows of 2048), in place.
// One block per row, 256 threads x 8 elems, values held in registers.
// ---------------------------------------------------------------------------
__global__ __launch_bounds__(256) void softmax_k()
{
    __shared__ float smax[8];
    __shared__ float ssum[8];
    float* p = g_s + (size_t)blockIdx.x * SEQ;
    const int t = threadIdx.x;

    float4 x0 = ((float4*)p)[t * 2];
    float4 x1 = ((float4*)p)[t * 2 + 1];

    float m = fmaxf(fmaxf(fmaxf(x0.x, x0.y), fmaxf(x0.z, x0.w)),
                    fmaxf(fmaxf(x1.x, x1.y), fmaxf(x1.z, x1.w)));
    #pragma unroll
    for (int o = 16; o > 0; o >>= 1) m = fmaxf(m, __shfl_xor_sync(0xffffffffu, m, o));
    if ((t & 31) == 0) smax[t >> 5] = m;
    __syncthreads();
    float rm = smax[0];
    #pragma unroll
    for (int i = 1; i < 8; i++) rm = fmaxf(rm, smax[i]);

    x0.x = __expf(x0.x - rm); x0.y = __expf(x0.y - rm);
    x0.z = __expf(x0.z - rm); x0.w = __expf(x0.w - rm);
    x1.x = __expf(x1.x - rm); x1.y = __expf(x1.y - rm);
    x1.z = __expf(x1.z - rm); x1.w = __expf(x1.w - rm);

    float s = x0.x + x0.y + x0.z + x0.w + x1.x + x1.y + x1.z + x1.w;
    #pragma unroll
    for (int o = 16; o > 0; o >>= 1) s += __shfl_xor_sync(0xffffffffu, s, o);
    if ((t & 31) == 0) ssum[t >> 5] = s;
    __syncthreads();
    float tot = ssum[0];
    #pragma unroll
    for (int i = 1; i < 8; i++) tot += ssum[i];
    const float inv = 1.0f / tot;

    x0.x *= inv; x0.y *= inv; x0.z *= inv; x0.w *= inv;
    x1.x *= inv; x1.y *= inv; x1.z *= inv; x1.w *= inv;
    ((float4*)p)[t * 2]     = x0;
    ((float4*)p)[t * 2 + 1] = x1;
}

// ---------------------------------------------------------------------------
// Kernel 5: batched PV   O[bh][2048,64] = P[bh][2048,2048] @ V[bh][2048,64]
// 256x64 tile, BK=8, 256 threads, 8x8 per thread.
// Epilogue writes directly into [b, n, h*64+d] layout (g_oc).
// ---------------------------------------------------------------------------
__global__ __launch_bounds__(256, 2) void gemm_pv()
{
    __shared__ float As[8][256];
    __shared__ float Bs[8][64];
    const int tid = threadIdx.x;
    const int tx = tid & 7, ty = tid >> 3;    // 8 x 32 thread grid
    const int bm = blockIdx.x * 256;
    const int bh = blockIdx.z;

    const float* P = g_s + (size_t)bh * SEQ * SEQ;
    const float* V = g_v + (size_t)bh * SEQ * DHEAD;

    float acc[8][8] = {};
    const int bk = tid >> 4, bnn = (tid & 15) * 4;

    for (int k0 = 0; k0 < SEQ; k0 += 8) {
        float4 a0 = *(const float4*)&P[(size_t)(bm + tid) * SEQ + k0];
        float4 a1 = *(const float4*)&P[(size_t)(bm + tid) * SEQ + k0 + 4];
        As[0][tid] = a0.x; As[1][tid] = a0.y; As[2][tid] = a0.z; As[3][tid] = a0.w;
        As[4][tid] = a1.x; As[5][tid] = a1.y; As[6][tid] = a1.z; As[7][tid] = a1.w;
        if (tid < 128) {
            *(float4*)&Bs[bk][bnn] = *(const float4*)&V[(size_t)(k0 + bk) * DHEAD + bnn];
        }
        __syncthreads();
        #pragma unroll
        for (int kk = 0; kk < 8; kk++) {
            float a[8], b[8];
            *(float4*)&a[0] = *(const float4*)&As[kk][ty * 8];
            *(float4*)&a[4] = *(const float4*)&As[kk][ty * 8 + 4];
            *(float4*)&b[0] = *(const float4*)&Bs[kk][tx * 8];
            *(float4*)&b[4] = *(const float4*)&Bs[kk][tx * 8 + 4];
            #pragma unroll
            for (int i = 0; i < 8; i++)
                #pragma unroll
                for (int j = 0; j < 8; j++)
                    acc[i][j] = fmaf(a[i], b[j], acc[i][j]);
        }
        __syncthreads();
    }

    const int b = bh >> 4, h = bh & 15;
    #pragma unroll
    for (int i = 0; i < 8; i++) {
        const int n = bm + ty * 8 + i;
        float* pd = g_oc + ((size_t)(b * SEQ + n) * DIMM + h * DHEAD + tx * 8);
        *(float4*)pd       = make_float4(acc[i][0], acc[i][1], acc[i][2], acc[i][3]);
        *(float4*)(pd + 4) = make_float4(acc[i][4], acc[i][5], acc[i][6], acc[i][7]);
    }
}

// ---------------------------------------------------------------------------
// Kernel 6: output projection  out[8192,1024] = g_oc[8192,1024] @ w_out[1024,1024]
// Same 128x128 core as gemm_qkv, plain epilogue.
// ---------------------------------------------------------------------------
__global__ __launch_bounds__(256, 2) void gemm_out(const float* __restrict__ B,
                                                   float* __restrict__ C)
{
    __shared__ float As[8][128];
    __shared__ float Bs[8][128];
    const int tid = threadIdx.x;
    const int tx = tid & 15, ty = tid >> 4;
    const int bm = blockIdx.y * 128, bn = blockIdx.x * 128;
    const int K = DIMM, N = DIMM;

    float acc[8][8] = {};
    const int a_row = tid >> 1, a_k = (tid & 1) * 4;
    const int b_k = tid >> 5, b_n = (tid & 31) * 4;
    const float* Aptr = g_oc + (size_t)(bm + a_row) * K + a_k;
    const float* Bptr = B + (size_t)b_k * N + bn + b_n;

    float4 av = *(const float4*)(Aptr);
    float4 bv = *(const float4*)(Bptr);

    for (int k0 = 0; k0 < K; k0 += 8) {
        As[a_k + 0][a_row] = av.x;
        As[a_k + 1][a_row] = av.y;
        As[a_k + 2][a_row] = av.z;
        As[a_k + 3][a_row] = av.w;
        *(float4*)&Bs[b_k][b_n] = bv;
        __syncthreads();

        float4 av_n, bv_n;
        if (k0 + 8 < K) {
            av_n = *(const float4*)(Aptr + k0 + 8);
            bv_n = *(const float4*)(Bptr + (size_t)(k0 + 8) * N);
        }

        #pragma unroll
        for (int kk = 0; kk < 8; kk++) {
            float a[8], b[8];
            *(float4*)&a[0] = *(const float4*)&As[kk][ty * 8];
            *(float4*)&a[4] = *(const float4*)&As[kk][ty * 8 + 4];
            *(float4*)&b[0] = *(const float4*)&Bs[kk][tx * 8];
            *(float4*)&b[4] = *(const float4*)&Bs[kk][tx * 8 + 4];
            #pragma unroll
            for (int i = 0; i < 8; i++)
                #pragma unroll
                for (int j = 0; j < 8; j++)
                    acc[i][j] = fmaf(a[i], b[j], acc[i][j]);
        }
        __syncthreads();
        av = av_n; bv = bv_n;
    }

    #pragma unroll
    for (int i = 0; i < 8; i++) {
        const int r = bm + ty * 8 + i;
        float* pd = C + (size_t)r * N + bn + tx * 8;
        *(float4*)pd       = make_float4(acc[i][0], acc[i][1], acc[i][2], acc[i][3]);
        *(float4*)(pd + 4) = make_float4(acc[i][4], acc[i][5], acc[i][6], acc[i][7]);
    }
}

// ---------------------------------------------------------------------------
// Launch pipeline (graph-capturable: kernel launches only, default stream)
// ---------------------------------------------------------------------------
extern "C" void kernel_launch(void* const* d_in, const int* in_sizes, int n_in,
                              void* d_out, int out_size)
{
    const float* x     = (const float*)d_in[0];
    const float* gamma = (const float*)d_in[1];
    const float* beta  = (const float*)d_in[2];
    const float* w_qkv = (const float*)d_in[3];
    const float* w_out = (const float*)d_in[4];
    float* out = (float*)d_out;

    ln_kernel<<<ROWS, 256>>>(x, gamma, beta);
    gemm_qkv<<<dim3(NQKV / 128, ROWS / 128), 256>>>(w_qkv);
    gemm_qk<<<dim3(SEQ / 128, SEQ / 128, BH), 256>>>();
    softmax_k<<<BH * SEQ, 256>>>();
    gemm_pv<<<dim3(SEQ / 256, 1, BH), 256>>>();
    gemm_out<<<dim3(DIMM / 128, ROWS / 128), 256>>>(w_out, out);
}